// round 15
// baseline (speedup 1.0000x reference)
#include <cuda_runtime.h>
#include <cuda_bf16.h>
#include <math_constants.h>

// ---------------- problem constants ----------------
#define NN   4096
#define DD   128
#define HH   4
#define DHH  32
#define DFF  2048
#define HID  256
#define OUTD 64
#define EE   131072
#define LNEPS 1e-5f
#define FSPLIT 4
#define ZSPLIT 2
#define QB   128                      // queries per attention block
#define KT_PER ((NN / 64) / ZSPLIT)   // 32 key tiles per split

typedef unsigned u32;

// q pre-scale: 1/sqrt(dh) * log2(e)  (attention uses ex2 directly)
#define QSCALE (0.17677669529663687f * 1.4426950408889634f)

// ---------------- helpers ----------------
__device__ __forceinline__ unsigned smem_u32(const void* p) {
    unsigned a;
    asm("{ .reg .u64 t; cvta.to.shared.u64 t, %1; cvt.u32.u64 %0, t; }"
        : "=r"(a) : "l"(p));
    return a;
}
__device__ __forceinline__ void cp16(u32 saddr, const void* gptr) {
    asm volatile("cp.async.ca.shared.global [%0], [%1], 16;"
                 :: "r"(saddr), "l"(gptr) : "memory");
}
__device__ __forceinline__ void cpcommit() {
    asm volatile("cp.async.commit_group;" ::: "memory");
}
__device__ __forceinline__ void cpwait0() {
    asm volatile("cp.async.wait_group 0;" ::: "memory");
}
__device__ __forceinline__ void cpwait1() {
    asm volatile("cp.async.wait_group 1;" ::: "memory");
}
// round-to-nearest tf32 conversion (keeps error unbiased)
__device__ __forceinline__ u32 f2tf(float x) {
    u32 u; asm("cvt.rna.tf32.f32 %0, %1;" : "=r"(u) : "f"(x));
    return u;
}
__device__ __forceinline__ float ex2(float x) {
    float y; asm("ex2.approx.ftz.f32 %0, %1;" : "=f"(y) : "f"(x));
    return y;
}
__device__ __forceinline__ void mma_tf32(float& d0, float& d1, float& d2, float& d3,
                                         u32 a0, u32 a1, u32 a2, u32 a3,
                                         u32 b0, u32 b1) {
    asm volatile(
        "mma.sync.aligned.m16n8k8.row.col.f32.tf32.tf32.f32 "
        "{%0,%1,%2,%3}, {%4,%5,%6,%7}, {%8,%9}, {%0,%1,%2,%3};\n"
        : "+f"(d0), "+f"(d1), "+f"(d2), "+f"(d3)
        : "r"(a0), "r"(a1), "r"(a2), "r"(a3), "r"(b0), "r"(b1));
}

// ---------------- scratch ----------------
__device__ float g_qkv[NN * 384];
__device__ float g_tmp[NN * DD];     // GCN agg buffer
__device__ float g_y[NN * DD];
__device__ float g_mid[NN * DFF];
__device__ float g_z[NN * DD];
__device__ float g_f2[FSPLIT * NN * DD];
__device__ float g_hw[NN * HID];
__device__ float g_h1[NN * HID];
__device__ float g_h2[NN * HID];
__device__ float g_pl[ZSPLIT * HH * NN];
__device__ float g_pacc[ZSPLIT * HH * NN * 32];
__device__ float g_dinv[NN];
__device__ int   g_cnt[NN];
__device__ int   g_rowptr[NN + 1];
__device__ int   g_fillpos[NN];
__device__ int   g_col[EE];
__device__ float g_w[EE];            // precomputed edge weights dinv[s]*dinv[d]

// ======================================================================
// tf32 tensor-core GEMM with cp.async double buffering (proven config).
// C = A[M,K]*B[Nc,K]^T (+bias)(+relu). Block tile BM x 64, BK=32.
// mode=1 (qkv): q columns pre-scaled by QSCALE, whole output tf32-rounded.
// ======================================================================
#define STR 44   // smem row stride in floats

template<int BM>
__global__ void __launch_bounds__(BM * 2) gemm_tc(
    const float* __restrict__ A, const float* __restrict__ B,
    const float* __restrict__ bias, float* __restrict__ C,
    int M, int Nc, int K, int relu, int kslice, int mode)
{
    extern __shared__ float smem[];
    float* As = smem;                  // [2][BM][STR]
    float* Bs = smem + 2 * BM * STR;   // [2][64][STR]
    const int THREADS = BM * 2;

    const int tid = threadIdx.x;
    const int wid = tid >> 5, lane = tid & 31;
    const int g = lane >> 2, t = lane & 3;
    const int warp_m = wid >> 1, warp_n = wid & 1;
    const int row0 = blockIdx.y * BM, col0 = blockIdx.x * 64;
    const int kbeg = blockIdx.z * kslice;
    const int niter = kslice / 32;
    C += (size_t)blockIdx.z * M * Nc;

    const u32 sAa = smem_u32(As), sBa = smem_u32(Bs);

    float acc[2][4][4];
#pragma unroll
    for (int mt = 0; mt < 2; mt++)
#pragma unroll
        for (int nt = 0; nt < 4; nt++)
#pragma unroll
            for (int j = 0; j < 4; j++) acc[mt][nt][j] = 0.0f;

    auto issue = [&](int it, int buf) {
        const float* abase = A + (size_t)row0 * K + kbeg + it * 32;
        u32 ad = sAa + buf * BM * STR * 4;
#pragma unroll
        for (int i = 0; i < 4; i++) {
            int c = tid + i * THREADS;          // BM*8 chunks
            int rr = c >> 3, kc = (c & 7) * 4;
            cp16(ad + (rr * STR + kc) * 4, abase + (size_t)rr * K + kc);
        }
        const float* bbase = B + (size_t)col0 * K + kbeg + it * 32;
        u32 bd = sBa + buf * 64 * STR * 4;
#pragma unroll
        for (int i = 0; i < 512 / (BM * 2); i++) {
            int c = tid + i * THREADS;          // 512 chunks
            int rr = c >> 3, kc = (c & 7) * 4;
            cp16(bd + (rr * STR + kc) * 4, bbase + (size_t)rr * K + kc);
        }
        cpcommit();
    };

    issue(0, 0);
    for (int it = 0; it < niter; it++) {
        if (it + 1 < niter) issue(it + 1, (it + 1) & 1);
        if (it + 1 < niter) cpwait1(); else cpwait0();
        __syncthreads();

        const float* Ab = As + (it & 1) * BM * STR;
        const float* Bb = Bs + (it & 1) * 64 * STR;
#pragma unroll
        for (int ks = 0; ks < 4; ks++) {
            u32 af[2][4];
#pragma unroll
            for (int mt = 0; mt < 2; mt++) {
                int rb = warp_m * 32 + mt * 16;
                af[mt][0] = f2tf(Ab[(rb + g) * STR + ks * 8 + t]);
                af[mt][1] = f2tf(Ab[(rb + g + 8) * STR + ks * 8 + t]);
                af[mt][2] = f2tf(Ab[(rb + g) * STR + ks * 8 + t + 4]);
                af[mt][3] = f2tf(Ab[(rb + g + 8) * STR + ks * 8 + t + 4]);
            }
#pragma unroll
            for (int nt = 0; nt < 4; nt++) {
                int nb = warp_n * 32 + nt * 8;
                u32 b0 = f2tf(Bb[(nb + g) * STR + ks * 8 + t]);
                u32 b1 = f2tf(Bb[(nb + g) * STR + ks * 8 + t + 4]);
#pragma unroll
                for (int mt = 0; mt < 2; mt++)
                    mma_tf32(acc[mt][nt][0], acc[mt][nt][1], acc[mt][nt][2], acc[mt][nt][3],
                             af[mt][0], af[mt][1], af[mt][2], af[mt][3], b0, b1);
            }
        }
        __syncthreads();
    }

#pragma unroll
    for (int mt = 0; mt < 2; mt++) {
        int r0 = row0 + warp_m * 32 + mt * 16 + g;
#pragma unroll
        for (int nt = 0; nt < 4; nt++) {
            int c0i = col0 + warp_n * 32 + nt * 8 + 2 * t;
            float b0 = 0.f, b1 = 0.f;
            if (bias) { b0 = bias[c0i]; b1 = bias[c0i + 1]; }
            float v0 = acc[mt][nt][0] + b0, v1 = acc[mt][nt][1] + b1;
            float v2 = acc[mt][nt][2] + b0, v3 = acc[mt][nt][3] + b1;
            if (relu) {
                v0 = fmaxf(v0, 0.f); v1 = fmaxf(v1, 0.f);
                v2 = fmaxf(v2, 0.f); v3 = fmaxf(v3, 0.f);
            }
            if (mode) {   // qkv: pre-round (and pre-scale q by QSCALE)
                float s = (c0i < DD) ? QSCALE : 1.0f;
                v0 = __uint_as_float(f2tf(v0 * s));
                v1 = __uint_as_float(f2tf(v1 * s));
                v2 = __uint_as_float(f2tf(v2 * s));
                v3 = __uint_as_float(f2tf(v3 * s));
            }
            *(float2*)&C[(size_t)r0 * Nc + c0i] = make_float2(v0, v1);
            *(float2*)&C[(size_t)(r0 + 8) * Nc + c0i] = make_float2(v2, v3);
        }
    }
}

// ======================================================================
// Wide tf32 GEMM: block tile 128x128, BK=32, 256 threads (8 warps 4x2),
// warp tile 32x64 = 2 m16 x 8 n8. For big-N GEMMs (ffn1).
// ======================================================================
__global__ void __launch_bounds__(256) gemm_tc_w(
    const float* __restrict__ A, const float* __restrict__ B,
    const float* __restrict__ bias, float* __restrict__ C,
    int M, int Nc, int K, int relu)
{
    extern __shared__ float smem[];
    float* As = smem;                    // [2][128][STR]
    float* Bs = smem + 2 * 128 * STR;    // [2][128][STR]

    const int tid = threadIdx.x;
    const int wid = tid >> 5, lane = tid & 31;
    const int g = lane >> 2, t = lane & 3;
    const int warp_m = wid >> 1, warp_n = wid & 1;
    const int row0 = blockIdx.y * 128, col0 = blockIdx.x * 128;
    const int niter = K / 32;

    const u32 sAa = smem_u32(As), sBa = smem_u32(Bs);

    float acc[2][8][4];
#pragma unroll
    for (int mt = 0; mt < 2; mt++)
#pragma unroll
        for (int nt = 0; nt < 8; nt++)
#pragma unroll
            for (int j = 0; j < 4; j++) acc[mt][nt][j] = 0.0f;

    auto issue = [&](int it, int buf) {
        const float* abase = A + (size_t)row0 * K + it * 32;
        u32 ad = sAa + buf * 128 * STR * 4;
#pragma unroll
        for (int i = 0; i < 4; i++) {
            int c = tid + i * 256;              // 1024 chunks
            int rr = c >> 3, kc = (c & 7) * 4;
            cp16(ad + (rr * STR + kc) * 4, abase + (size_t)rr * K + kc);
        }
        const float* bbase = B + (size_t)col0 * K + it * 32;
        u32 bd = sBa + buf * 128 * STR * 4;
#pragma unroll
        for (int i = 0; i < 4; i++) {
            int c = tid + i * 256;              // 1024 chunks
            int rr = c >> 3, kc = (c & 7) * 4;
            cp16(bd + (rr * STR + kc) * 4, bbase + (size_t)rr * K + kc);
        }
        cpcommit();
    };

    issue(0, 0);
    for (int it = 0; it < niter; it++) {
        if (it + 1 < niter) issue(it + 1, (it + 1) & 1);
        if (it + 1 < niter) cpwait1(); else cpwait0();
        __syncthreads();

        const float* Ab = As + (it & 1) * 128 * STR;
        const float* Bb = Bs + (it & 1) * 128 * STR;
#pragma unroll
        for (int ks = 0; ks < 4; ks++) {
            u32 af[2][4];
#pragma unroll
            for (int mt = 0; mt < 2; mt++) {
                int rb = warp_m * 32 + mt * 16;
                af[mt][0] = f2tf(Ab[(rb + g) * STR + ks * 8 + t]);
                af[mt][1] = f2tf(Ab[(rb + g + 8) * STR + ks * 8 + t]);
                af[mt][2] = f2tf(Ab[(rb + g) * STR + ks * 8 + t + 4]);
                af[mt][3] = f2tf(Ab[(rb + g + 8) * STR + ks * 8 + t + 4]);
            }
#pragma unroll
            for (int nt = 0; nt < 8; nt++) {
                int nb = warp_n * 64 + nt * 8;
                u32 b0 = f2tf(Bb[(nb + g) * STR + ks * 8 + t]);
                u32 b1 = f2tf(Bb[(nb + g) * STR + ks * 8 + t + 4]);
#pragma unroll
                for (int mt = 0; mt < 2; mt++)
                    mma_tf32(acc[mt][nt][0], acc[mt][nt][1], acc[mt][nt][2], acc[mt][nt][3],
                             af[mt][0], af[mt][1], af[mt][2], af[mt][3], b0, b1);
            }
        }
        __syncthreads();
    }

#pragma unroll
    for (int mt = 0; mt < 2; mt++) {
        int r0 = row0 + warp_m * 32 + mt * 16 + g;
#pragma unroll
        for (int nt = 0; nt < 8; nt++) {
            int c0i = col0 + warp_n * 64 + nt * 8 + 2 * t;
            float b0 = 0.f, b1 = 0.f;
            if (bias) { b0 = bias[c0i]; b1 = bias[c0i + 1]; }
            float v0 = acc[mt][nt][0] + b0, v1 = acc[mt][nt][1] + b1;
            float v2 = acc[mt][nt][2] + b0, v3 = acc[mt][nt][3] + b1;
            if (relu) {
                v0 = fmaxf(v0, 0.f); v1 = fmaxf(v1, 0.f);
                v2 = fmaxf(v2, 0.f); v3 = fmaxf(v3, 0.f);
            }
            *(float2*)&C[(size_t)r0 * Nc + c0i] = make_float2(v0, v1);
            *(float2*)&C[(size_t)(r0 + 8) * Nc + c0i] = make_float2(v2, v3);
        }
    }
}

// ======================================================================
// Flash attention, tf32 mma, cp.async double-buffered K/V, K-split x2.
// Fixed-base softmax via ex2 (q pre-scaled by log2e/sqrt(dh)).
// P stored raw fp32 via st.shared.v2. 128 queries x head x half keys.
// ======================================================================
#define PSTR 36   // sP row stride (36 mod 32 == 4 -> conflict-free frag reads)

__global__ void __launch_bounds__(256) attn_tc(const float* __restrict__ qkv,
                                               float* __restrict__ pl,
                                               float* __restrict__ pacc)
{
    extern __shared__ float smem[];
    float* sK = smem;                   // [2][64][STR]
    float* sV = smem + 2 * 64 * STR;    // [2][64][STR]
    float* sQ = smem + 4 * 64 * STR;    // [QB][STR], reused as sP [QB][PSTR]
    float* sPf = sQ;
    u32*   sP = (u32*)sQ;

    const int h = blockIdx.y, z = blockIdx.z;
    const int q0 = blockIdx.x * QB;
    const int tid = threadIdx.x;
    const int wid = tid >> 5, lane = tid & 31;
    const int g = lane >> 2, t = lane & 3;
    const int rb = wid * 16;

    const int qoff = h * 32;
    const int koff = DD + h * 32;
    const int voff = 2 * DD + h * 32;
    const int kt_beg = z * KT_PER, kt_end = kt_beg + KT_PER;

    const u32 sKa = smem_u32(sK), sVa = smem_u32(sV), sQa = smem_u32(sQ);

    // stage Q
#pragma unroll
    for (int i = 0; i < QB * 8 / 256; i++) {
        int c = tid + i * 256;
        int rr = c >> 3, kc = (c & 7) * 4;
        cp16(sQa + (rr * STR + kc) * 4, &qkv[(size_t)(q0 + rr) * 384 + qoff + kc]);
    }
    cpcommit();

    auto issueKV = [&](int kt, int buf) {
#pragma unroll
        for (int i = 0; i < 2; i++) {
            int c = tid + i * 256;                  // 512 chunks (64 rows x 8)
            int rr = c >> 3, kc = (c & 7) * 4;
            const float* base = &qkv[(size_t)(kt * 64 + rr) * 384];
            cp16(sKa + (buf * 64 * STR + rr * STR + kc) * 4, base + koff + kc);
            cp16(sVa + (buf * 64 * STR + rr * STR + kc) * 4, base + voff + kc);
        }
        cpcommit();
    };

    issueKV(kt_beg, 0);
    cpwait1();
    __syncthreads();

    // Q fragments (already tf32-rounded and QSCALE-scaled)
    u32 qf[4][4];
#pragma unroll
    for (int ks = 0; ks < 4; ks++) {
        qf[ks][0] = __float_as_uint(sQ[(rb + g) * STR + ks * 8 + t]);
        qf[ks][1] = __float_as_uint(sQ[(rb + g + 8) * STR + ks * 8 + t]);
        qf[ks][2] = __float_as_uint(sQ[(rb + g) * STR + ks * 8 + t + 4]);
        qf[ks][3] = __float_as_uint(sQ[(rb + g + 8) * STR + ks * 8 + t + 4]);
    }

    float O[4][4];
#pragma unroll
    for (int nt = 0; nt < 4; nt++)
#pragma unroll
        for (int j = 0; j < 4; j++) O[nt][j] = 0.0f;
    float lg = 0.0f, lg8 = 0.0f;

    for (int kt = kt_beg; kt < kt_end; kt++) {
        if (kt + 1 < kt_end) issueKV(kt + 1, (kt + 1) & 1);
        if (kt + 1 < kt_end) cpwait1(); else cpwait0();
        __syncthreads();

        const float* K_ = sK + (kt & 1) * 64 * STR;
        const float* V_ = sV + (kt & 1) * 64 * STR;

        // S = Q K^T (16 x 64 per warp), base-2 domain
        float sc[8][4];
#pragma unroll
        for (int nt = 0; nt < 8; nt++)
#pragma unroll
            for (int j = 0; j < 4; j++) sc[nt][j] = 0.0f;
#pragma unroll
        for (int ks = 0; ks < 4; ks++) {
#pragma unroll
            for (int nt = 0; nt < 8; nt++) {
                u32 b0 = __float_as_uint(K_[(nt * 8 + g) * STR + ks * 8 + t]);
                u32 b1 = __float_as_uint(K_[(nt * 8 + g) * STR + ks * 8 + t + 4]);
                mma_tf32(sc[nt][0], sc[nt][1], sc[nt][2], sc[nt][3],
                         qf[ks][0], qf[ks][1], qf[ks][2], qf[ks][3], b0, b1);
            }
        }

        // P = 2^S -> sP via v2 stores; accumulate row sums in fp32
#pragma unroll
        for (int nt = 0; nt < 8; nt++) {
            float p0 = ex2(sc[nt][0]);
            float p1 = ex2(sc[nt][1]);
            float p2 = ex2(sc[nt][2]);
            float p3 = ex2(sc[nt][3]);
            lg += p0 + p1; lg8 += p2 + p3;
            int cc = nt * 8 + 2 * t;
            *(float2*)&sPf[(rb + g) * PSTR + cc] = make_float2(p0, p1);
            *(float2*)&sPf[(rb + g + 8) * PSTR + cc] = make_float2(p2, p3);
        }
        __syncwarp();

        // O += P V
#pragma unroll
        for (int ks = 0; ks < 8; ks++) {
            u32 a0 = sP[(rb + g) * PSTR + ks * 8 + t];
            u32 a1 = sP[(rb + g + 8) * PSTR + ks * 8 + t];
            u32 a2 = sP[(rb + g) * PSTR + ks * 8 + t + 4];
            u32 a3 = sP[(rb + g + 8) * PSTR + ks * 8 + t + 4];
#pragma unroll
            for (int nt = 0; nt < 4; nt++) {
                u32 b0 = __float_as_uint(V_[(ks * 8 + t) * STR + nt * 8 + g]);
                u32 b1 = __float_as_uint(V_[(ks * 8 + t + 4) * STR + nt * 8 + g]);
                mma_tf32(O[nt][0], O[nt][1], O[nt][2], O[nt][3],
                         a0, a1, a2, a3, b0, b1);
            }
        }
        __syncthreads();
    }

    // quad-reduce l; write unnormalized partials
    lg  += __shfl_xor_sync(0xffffffffu, lg, 1);
    lg  += __shfl_xor_sync(0xffffffffu, lg, 2);
    lg8 += __shfl_xor_sync(0xffffffffu, lg8, 1);
    lg8 += __shfl_xor_sync(0xffffffffu, lg8, 2);

    const int prow = (z * HH + h) * NN + q0 + rb + g;   // row index in partials
    if (t == 0) {
        pl[prow] = lg;       pl[prow + 8] = lg8;
    }
    float* op0 = pacc + (size_t)prow * 32;
    float* op8 = pacc + (size_t)(prow + 8) * 32;
#pragma unroll
    for (int nt = 0; nt < 4; nt++) {
        int cc = nt * 8 + 2 * t;
        *(float2*)&op0[cc] = make_float2(O[nt][0], O[nt][1]);
        *(float2*)&op8[cc] = make_float2(O[nt][2], O[nt][3]);
    }
}

// ======================================================================
// Fused combine + out_proj + residual + LayerNorm1:
// y = LN(x + (ctx @ W^T + b)), ctx = (pacc0+pacc1)/(l0+l1).
// Block = 64 rows x FULL 128 cols (so LN is block-local). 256 threads,
// 8 warps (warp_m 0..3 x warp_n 0..1), warp tile 16x64 (8 n8 tiles).
// ======================================================================
__global__ void __launch_bounds__(256) outproj_ln_fused(
    const float* __restrict__ pl, const float* __restrict__ pacc,
    const float* __restrict__ W, const float* __restrict__ bias,
    const float* __restrict__ x,
    const float* __restrict__ lng, const float* __restrict__ lnb,
    float* __restrict__ Y)
{
    extern __shared__ float smem[];
    constexpr int AST = DD + 4;          // 132
    float* As  = smem;                   // [64][AST] ctx
    float* Bs  = smem + 64 * AST;        // [128][AST] weights
    float* red = smem + (64 + 128) * AST; // [64][2][2] LN partials

    const int tid = threadIdx.x;
    const int wid = tid >> 5, lane = tid & 31;
    const int g = lane >> 2, t = lane & 3;
    const int warp_m = wid >> 1, warp_n = wid & 1;
    const int row0 = blockIdx.x * 64;
    const u32 sBa = smem_u32(Bs);
    const int OFF = HH * NN;

    // issue B (all 128 weight rows) async first: 128*32 = 4096 chunks
#pragma unroll
    for (int i = 0; i < 16; i++) {
        int c = tid + i * 256;
        int rr = c >> 5, kc = (c & 31) * 4;
        cp16(sBa + (rr * AST + kc) * 4, W + (size_t)rr * DD + kc);
    }
    cpcommit();

    // stage A = normalized ctx from partials (overlaps B flight)
#pragma unroll
    for (int i = 0; i < 8; i++) {
        int c = tid + i * 256;                   // 2048 chunks
        int rr = c >> 5, kc = (c & 31) * 4;      // kc in [0,128)
        int h = kc >> 5, cc = kc & 31;
        int n = row0 + rr;
        int pr = h * NN + n;
        float l = pl[pr] + pl[OFF + pr];
        float inv = 1.0f / l;
        const float4 a0 = *(const float4*)&pacc[(size_t)pr * 32 + cc];
        const float4 a1 = *(const float4*)&pacc[(size_t)(OFF + pr) * 32 + cc];
        float4 v;
        v.x = (a0.x + a1.x) * inv; v.y = (a0.y + a1.y) * inv;
        v.z = (a0.z + a1.z) * inv; v.w = (a0.w + a1.w) * inv;
        *(float4*)&As[rr * AST + kc] = v;
    }
    cpwait0();
    __syncthreads();

    float acc[8][4];
#pragma unroll
    for (int nt = 0; nt < 8; nt++)
#pragma unroll
        for (int j = 0; j < 4; j++) acc[nt][j] = 0.0f;

#pragma unroll
    for (int ks = 0; ks < DD / 8; ks++) {
        int rbm = warp_m * 16;
        u32 a0 = f2tf(As[(rbm + g) * AST + ks * 8 + t]);
        u32 a1 = f2tf(As[(rbm + g + 8) * AST + ks * 8 + t]);
        u32 a2 = f2tf(As[(rbm + g) * AST + ks * 8 + t + 4]);
        u32 a3 = f2tf(As[(rbm + g + 8) * AST + ks * 8 + t + 4]);
#pragma unroll
        for (int nt = 0; nt < 8; nt++) {
            int nb = warp_n * 64 + nt * 8;
            u32 b0 = f2tf(Bs[(nb + g) * AST + ks * 8 + t]);
            u32 b1 = f2tf(Bs[(nb + g) * AST + ks * 8 + t + 4]);
            mma_tf32(acc[nt][0], acc[nt][1], acc[nt][2], acc[nt][3],
                     a0, a1, a2, a3, b0, b1);
        }
    }

    // epilogue: v = acc + bias + x, then LN over the 128 cols of each row
    const int r0 = row0 + warp_m * 16 + g;       // global rows r0, r0+8
    const int rl0 = warp_m * 16 + g;             // local rows
    float s0 = 0.f, q0v = 0.f, s8 = 0.f, q8v = 0.f;
#pragma unroll
    for (int nt = 0; nt < 8; nt++) {
        int c0i = warp_n * 64 + nt * 8 + 2 * t;
        float b0 = bias[c0i], b1 = bias[c0i + 1];
        float2 x0 = *(const float2*)&x[(size_t)r0 * DD + c0i];
        float2 x8 = *(const float2*)&x[(size_t)(r0 + 8) * DD + c0i];
        acc[nt][0] += b0 + x0.x;  acc[nt][1] += b1 + x0.y;
        acc[nt][2] += b0 + x8.x;  acc[nt][3] += b1 + x8.y;
        s0  += acc[nt][0] + acc[nt][1];
        q0v += acc[nt][0] * acc[nt][0] + acc[nt][1] * acc[nt][1];
        s8  += acc[nt][2] + acc[nt][3];
        q8v += acc[nt][2] * acc[nt][2] + acc[nt][3] * acc[nt][3];
    }
    // reduce over the 4 t-lanes (same g)
#pragma unroll
    for (int off = 1; off <= 2; off <<= 1) {
        s0  += __shfl_xor_sync(0xffffffffu, s0, off);
        q0v += __shfl_xor_sync(0xffffffffu, q0v, off);
        s8  += __shfl_xor_sync(0xffffffffu, s8, off);
        q8v += __shfl_xor_sync(0xffffffffu, q8v, off);
    }
    if (t == 0) {
        red[(rl0 * 2 + warp_n) * 2 + 0] = s0;
        red[(rl0 * 2 + warp_n) * 2 + 1] = q0v;
        red[((rl0 + 8) * 2 + warp_n) * 2 + 0] = s8;
        red[((rl0 + 8) * 2 + warp_n) * 2 + 1] = q8v;
    }
    __syncthreads();
    float st0 = red[(rl0 * 2) * 2] + red[(rl0 * 2 + 1) * 2];
    float qt0 = red[(rl0 * 2) * 2 + 1] + red[(rl0 * 2 + 1) * 2 + 1];
    float st8 = red[((rl0 + 8) * 2) * 2] + red[((rl0 + 8) * 2 + 1) * 2];
    float qt8 = red[((rl0 + 8) * 2) * 2 + 1] + red[((rl0 + 8) * 2 + 1) * 2 + 1];
    float mu0 = st0 * (1.0f / DD), mu8 = st8 * (1.0f / DD);
    float iv0 = rsqrtf(qt0 * (1.0f / DD) - mu0 * mu0 + LNEPS);
    float iv8 = rsqrtf(qt8 * (1.0f / DD) - mu8 * mu8 + LNEPS);

#pragma unroll
    for (int nt = 0; nt < 8; nt++) {
        int c0i = warp_n * 64 + nt * 8 + 2 * t;
        float2 gw = *(const float2*)&lng[c0i];
        float2 bw = *(const float2*)&lnb[c0i];
        float y0 = (acc[nt][0] - mu0) * iv0 * gw.x + bw.x;
        float y1 = (acc[nt][1] - mu0) * iv0 * gw.y + bw.y;
        float y2 = (acc[nt][2] - mu8) * iv8 * gw.x + bw.x;
        float y3 = (acc[nt][3] - mu8) * iv8 * gw.y + bw.y;
        *(float2*)&Y[(size_t)r0 * DD + c0i] = make_float2(y0, y1);
        *(float2*)&Y[(size_t)(r0 + 8) * DD + c0i] = make_float2(y2, y3);
    }
}

// ---------------- residual + sum(FSPLIT) + LayerNorm ----------------------
__global__ void __launch_bounds__(256) ln_sum4_kernel(
    const float* __restrict__ x, const float* __restrict__ parts,
    const float* __restrict__ fb, const float* __restrict__ g,
    const float* __restrict__ b, float* __restrict__ out)
{
    int row = blockIdx.x * 8 + (threadIdx.x >> 5);
    int lane = threadIdx.x & 31;
    size_t i = (size_t)row * 32 + lane;
    const size_t ps = (size_t)NN * 32;    // float4 stride between partials
    const float4* p4 = (const float4*)parts;
    float4 v = ((const float4*)x)[i];
    float4 fbv = ((const float4*)fb)[lane];
    v.x += fbv.x; v.y += fbv.y; v.z += fbv.z; v.w += fbv.w;
#pragma unroll
    for (int zz = 0; zz < FSPLIT; zz++) {
        float4 p = p4[i + zz * ps];
        v.x += p.x; v.y += p.y; v.z += p.z; v.w += p.w;
    }

    float s = v.x + v.y + v.z + v.w;
    float s2 = v.x * v.x + v.y * v.y + v.z * v.z + v.w * v.w;
#pragma unroll
    for (int off = 16; off > 0; off >>= 1) {
        s  += __shfl_xor_sync(0xffffffffu, s, off);
        s2 += __shfl_xor_sync(0xffffffffu, s2, off);
    }
    float mu = s * (1.0f / DD);
    float var = s2 * (1.0f / DD) - mu * mu;
    float inv = rsqrtf(var + LNEPS);

    float4 gw = ((const float4*)g)[lane];
    float4 bw = ((const float4*)b)[lane];
    float4 o;
    o.x = (v.x - mu) * inv * gw.x + bw.x;
    o.y = (v.y - mu) * inv * gw.y + bw.y;
    o.z = (v.z - mu) * inv * gw.z + bw.z;
    o.w = (v.w - mu) * inv * gw.w + bw.w;
    ((float4*)out)[i] = o;
}

// ---------------- GCN graph preprocessing (side stream) --------------------
__global__ void zero_cnt_kernel() {
    g_cnt[blockIdx.x * 256 + threadIdx.x] = 0;
}
__global__ void count_kernel(const int* __restrict__ dst) {
    int e = blockIdx.x * blockDim.x + threadIdx.x;
    if (e < EE) atomicAdd(&g_cnt[dst[e]], 1);
}
__global__ void scan_kernel() {
    __shared__ int sh[1024];
    int t = threadIdx.x;
    int base = t * 4;
    int c0 = g_cnt[base + 0], c1 = g_cnt[base + 1];
    int c2 = g_cnt[base + 2], c3 = g_cnt[base + 3];
    g_dinv[base + 0] = rsqrtf((float)c0 + 1.0f);
    g_dinv[base + 1] = rsqrtf((float)c1 + 1.0f);
    g_dinv[base + 2] = rsqrtf((float)c2 + 1.0f);
    g_dinv[base + 3] = rsqrtf((float)c3 + 1.0f);
    int local = c0 + c1 + c2 + c3;
    sh[t] = local;
    __syncthreads();
    for (int off = 1; off < 1024; off <<= 1) {
        int v = (t >= off) ? sh[t - off] : 0;
        __syncthreads();
        sh[t] += v;
        __syncthreads();
    }
    int excl = sh[t] - local;
    int p0 = excl, p1 = excl + c0, p2 = p1 + c1, p3 = p2 + c2;
    g_rowptr[base + 0] = p0; g_rowptr[base + 1] = p1;
    g_rowptr[base + 2] = p2; g_rowptr[base + 3] = p3;
    g_fillpos[base + 0] = p0; g_fillpos[base + 1] = p1;
    g_fillpos[base + 2] = p2; g_fillpos[base + 3] = p3;
    if (t == 1023) g_rowptr[NN] = excl + local;
}
// fill also precomputes the edge weight w = dinv[src]*dinv[dst]
// (dinv is ready: scan runs before fill on the same stream)
__global__ void fill_kernel(const int* __restrict__ src, const int* __restrict__ dst) {
    int e = blockIdx.x * blockDim.x + threadIdx.x;
    if (e < EE) {
        int d = dst[e];
        int s = src[e];
        int pos = atomicAdd(&g_fillpos[d], 1);
        g_col[pos] = s;
        g_w[pos] = g_dinv[s] * g_dinv[d];
    }
}

// ---------------- GCN aggregation: gather over CSR -------------------------
// Edge weights precomputed -> single dependent gather (hw) per edge;
// col/w prefetched 1-deep (sequential, L2-friendly).
template<int F, bool RELU>
__global__ void gather_kernel(const float* __restrict__ hw,
                              const float* __restrict__ bias,
                              float* __restrict__ out)
{
    constexpr int TPR = F / 4;
    constexpr int RPB = 256 / TPR;
    int tid = threadIdx.x;
    int r = blockIdx.x * RPB + tid / TPR;
    int lane = tid % TPR;
    const float4* hw4 = (const float4*)hw;

    float dr = g_dinv[r];
    float4 acc = hw4[(size_t)r * TPR + lane];
    float selfw = dr * dr;
    acc.x *= selfw; acc.y *= selfw; acc.z *= selfw; acc.w *= selfw;

    int p0 = g_rowptr[r], p1 = g_rowptr[r + 1];
    if (p0 < p1) {
        int s = g_col[p0];
        float w = g_w[p0];
        float4 hv = hw4[(size_t)s * TPR + lane];
        for (int p = p0 + 1; p < p1; p++) {
            int s2 = g_col[p];
            float w2 = g_w[p];
            float4 hv2 = hw4[(size_t)s2 * TPR + lane];
            acc.x += w * hv.x; acc.y += w * hv.y;
            acc.z += w * hv.z; acc.w += w * hv.w;
            hv = hv2; w = w2;
        }
        acc.x += w * hv.x; acc.y += w * hv.y;
        acc.z += w * hv.z; acc.w += w * hv.w;
    }
    if (bias) {
        float4 bb = *(const float4*)&bias[lane * 4];
        acc.x += bb.x; acc.y += bb.y; acc.z += bb.z; acc.w += bb.w;
    }
    if (RELU) {
        acc.x = fmaxf(acc.x, 0.f); acc.y = fmaxf(acc.y, 0.f);
        acc.z = fmaxf(acc.z, 0.f); acc.w = fmaxf(acc.w, 0.f);
    }
    *(float4*)&out[(size_t)r * F + lane * 4] = acc;
}

// ---------------- launch ---------------------------------------------------
extern "C" void kernel_launch(void* const* d_in, const int* in_sizes, int n_in,
                              void* d_out, int out_size)
{
    const float* x          = (const float*)d_in[0];
    const int*   edge_index = (const int*)  d_in[1];
    const float* in_proj_w  = (const float*)d_in[2];
    const float* in_proj_b  = (const float*)d_in[3];
    const float* out_proj_w = (const float*)d_in[4];
    const float* out_proj_b = (const float*)d_in[5];
    const float* ln1_g      = (const float*)d_in[6];
    const float* ln1_b      = (const float*)d_in[7];
    const float* ffn_w1     = (const float*)d_in[8];
    const float* ffn_b1     = (const float*)d_in[9];
    const float* ffn_w2     = (const float*)d_in[10];
    const float* ffn_b2     = (const float*)d_in[11];
    const float* ln2_g      = (const float*)d_in[12];
    const float* ln2_b      = (const float*)d_in[13];
    const float* gcn1_w     = (const float*)d_in[14];
    const float* gcn1_b     = (const float*)d_in[15];
    const float* gcn2_w     = (const float*)d_in[16];
    const float* gcn2_b     = (const float*)d_in[17];
    const float* gcn3_w     = (const float*)d_in[18];
    const float* gcn3_b     = (const float*)d_in[19];
    float* out = (float*)d_out;

    const int* src = edge_index;
    const int* dst = edge_index + EE;

    float *p_qkv, *p_tmp, *p_y, *p_mid, *p_z, *p_f2, *p_hw, *p_h1, *p_h2;
    float *p_pl, *p_pacc;
    cudaGetSymbolAddress((void**)&p_qkv,  g_qkv);
    cudaGetSymbolAddress((void**)&p_tmp,  g_tmp);
    cudaGetSymbolAddress((void**)&p_y,    g_y);
    cudaGetSymbolAddress((void**)&p_mid,  g_mid);
    cudaGetSymbolAddress((void**)&p_z,    g_z);
    cudaGetSymbolAddress((void**)&p_f2,   g_f2);
    cudaGetSymbolAddress((void**)&p_hw,   g_hw);
    cudaGetSymbolAddress((void**)&p_h1,   g_h1);
    cudaGetSymbolAddress((void**)&p_h2,   g_h2);
    cudaGetSymbolAddress((void**)&p_pl,   g_pl);
    cudaGetSymbolAddress((void**)&p_pacc, g_pacc);

    const int SM_G128 = (2 * 128 * STR + 2 * 64 * STR) * 4;   // 67584
    const int SM_G64  = (2 * 64 * STR + 2 * 64 * STR) * 4;    // 45056
    const int SM_GW   = (4 * 128 * STR) * 4;                  // 90112
    const int SM_ATTN = (4 * 64 * STR + QB * STR) * 4;        // 67584
    const int SM_OPLN = ((64 + 128) * (DD + 4) + 64 * 4) * 4; // 102400

    cudaFuncSetAttribute(gemm_tc<128>, cudaFuncAttributeMaxDynamicSharedMemorySize, SM_G128);
    cudaFuncSetAttribute(gemm_tc<64>,  cudaFuncAttributeMaxDynamicSharedMemorySize, SM_G64);
    cudaFuncSetAttribute(gemm_tc_w,    cudaFuncAttributeMaxDynamicSharedMemorySize, SM_GW);
    cudaFuncSetAttribute(attn_tc,      cudaFuncAttributeMaxDynamicSharedMemorySize, SM_ATTN);
    cudaFuncSetAttribute(outproj_ln_fused, cudaFuncAttributeMaxDynamicSharedMemorySize, SM_OPLN);

    // side stream + fork/join events (created once on the uncaptured call)
    static cudaStream_t s2 = nullptr;
    static cudaEvent_t evFork = nullptr, evJoin = nullptr;
    if (s2 == nullptr) {
        cudaStreamCreateWithFlags(&s2, cudaStreamNonBlocking);
        cudaEventCreateWithFlags(&evFork, cudaEventDisableTiming);
        cudaEventCreateWithFlags(&evJoin, cudaEventDisableTiming);
    }

    // ---- fork: graph preprocessing on side stream ----
    cudaEventRecord(evFork, 0);
    cudaStreamWaitEvent(s2, evFork, 0);
    zero_cnt_kernel<<<NN / 256, 256, 0, s2>>>();
    count_kernel<<<EE / 256, 256, 0, s2>>>(dst);
    scan_kernel<<<1, 1024, 0, s2>>>();
    fill_kernel<<<EE / 256, 256, 0, s2>>>(src, dst);
    cudaEventRecord(evJoin, s2);

    // ---- transformer encoder layer (main stream) ----
    gemm_tc<128><<<dim3(6, 32), 256, SM_G128>>>(x, in_proj_w, in_proj_b, p_qkv,
                                                NN, 384, DD, 0, DD, 1);
    attn_tc<<<dim3(NN / QB, HH, ZSPLIT), 256, SM_ATTN>>>(p_qkv, p_pl, p_pacc);
    outproj_ln_fused<<<64, 256, SM_OPLN>>>(p_pl, p_pacc, out_proj_w, out_proj_b,
                                           x, ln1_g, ln1_b, p_y);
    gemm_tc_w<<<dim3(DFF / 128, 32), 256, SM_GW>>>(p_y, ffn_w1, ffn_b1, p_mid,
                                                   NN, DFF, DD, 1);
    gemm_tc<128><<<dim3(2, 32, FSPLIT), 256, SM_G128>>>(p_mid, ffn_w2, nullptr, p_f2,
                                                        NN, DD, DFF, 0, DFF / FSPLIT, 0);
    ln_sum4_kernel<<<NN / 8, 256>>>(p_y, p_f2, ffn_b2, ln2_g, ln2_b, p_z);

    // ---- join: CSR must be ready before the first gather ----
    cudaStreamWaitEvent(0, evJoin, 0);

    // ---- GCN layer 1: aggregate z (128-wide) first, then project ----
    gather_kernel<DD, false><<<NN / 8, 256>>>(p_z, nullptr, p_tmp);
    gemm_tc<64><<<dim3(4, 64), 128, SM_G64>>>(p_tmp, gcn1_w, gcn1_b, p_h1,
                                              NN, HID, DD, 1, DD, 0);

    // ---- GCN layer 2: project then aggregate (bias+relu in gather) ----
    gemm_tc<64><<<dim3(4, 64), 128, SM_G64>>>(p_h1, gcn2_w, nullptr, p_hw,
                                              NN, HID, HID, 0, HID, 0);
    gather_kernel<HID, true><<<NN / 4, 256>>>(p_hw, gcn2_b, p_h2);

    // ---- GCN layer 3: project (64-wide) then aggregate ----
    gemm_tc<64><<<dim3(1, 64), 128, SM_G64>>>(p_h2, gcn3_w, nullptr, p_hw,
                                              NN, OUTD, HID, 0, HID, 0);
    gather_kernel<OUTD, false><<<NN / 16, 256>>>(p_hw, gcn3_b, out);
}

// round 16
// speedup vs baseline: 1.0274x; 1.0274x over previous
#include <cuda_runtime.h>
#include <cuda_bf16.h>
#include <math_constants.h>

// ---------------- problem constants ----------------
#define NN   4096
#define DD   128
#define HH   4
#define DHH  32
#define DFF  2048
#define HID  256
#define OUTD 64
#define EE   131072
#define LNEPS 1e-5f
#define FSPLIT 4
#define ZSPLIT 2
#define QB   128                      // queries per attention block
#define KT_PER ((NN / 64) / ZSPLIT)   // 32 key tiles per split

typedef unsigned u32;

// q pre-scale: 1/sqrt(dh) * log2(e)  (attention uses ex2 directly)
#define QSCALE (0.17677669529663687f * 1.4426950408889634f)

// ---------------- helpers ----------------
__device__ __forceinline__ unsigned smem_u32(const void* p) {
    unsigned a;
    asm("{ .reg .u64 t; cvta.to.shared.u64 t, %1; cvt.u32.u64 %0, t; }"
        : "=r"(a) : "l"(p));
    return a;
}
__device__ __forceinline__ void cp16(u32 saddr, const void* gptr) {
    asm volatile("cp.async.ca.shared.global [%0], [%1], 16;"
                 :: "r"(saddr), "l"(gptr) : "memory");
}
__device__ __forceinline__ void cpcommit() {
    asm volatile("cp.async.commit_group;" ::: "memory");
}
__device__ __forceinline__ void cpwait0() {
    asm volatile("cp.async.wait_group 0;" ::: "memory");
}
__device__ __forceinline__ void cpwait1() {
    asm volatile("cp.async.wait_group 1;" ::: "memory");
}
// round-to-nearest tf32 conversion (keeps error unbiased)
__device__ __forceinline__ u32 f2tf(float x) {
    u32 u; asm("cvt.rna.tf32.f32 %0, %1;" : "=r"(u) : "f"(x));
    return u;
}
__device__ __forceinline__ float ex2(float x) {
    float y; asm("ex2.approx.ftz.f32 %0, %1;" : "=f"(y) : "f"(x));
    return y;
}
__device__ __forceinline__ void mma_tf32(float& d0, float& d1, float& d2, float& d3,
                                         u32 a0, u32 a1, u32 a2, u32 a3,
                                         u32 b0, u32 b1) {
    asm volatile(
        "mma.sync.aligned.m16n8k8.row.col.f32.tf32.tf32.f32 "
        "{%0,%1,%2,%3}, {%4,%5,%6,%7}, {%8,%9}, {%0,%1,%2,%3};\n"
        : "+f"(d0), "+f"(d1), "+f"(d2), "+f"(d3)
        : "r"(a0), "r"(a1), "r"(a2), "r"(a3), "r"(b0), "r"(b1));
}

// ---------------- scratch ----------------
__device__ float g_qkv[NN * 384];
__device__ float g_tmp[NN * DD];     // GCN agg buffer
__device__ float g_y[NN * DD];
__device__ float g_mid[NN * DFF];
__device__ float g_z[NN * DD];
__device__ float g_f2[FSPLIT * NN * DD];
__device__ float g_hw[NN * HID];
__device__ float g_h1[NN * HID];
__device__ float g_h2[NN * HID];
__device__ float g_pl[ZSPLIT * HH * NN];
__device__ float g_pacc[ZSPLIT * HH * NN * 32];
__device__ float g_dinv[NN];
__device__ int   g_cnt[NN];
__device__ int   g_rowptr[NN + 1];
__device__ int   g_fillpos[NN];
__device__ int   g_col[EE];

// ======================================================================
// tf32 tensor-core GEMM with cp.async double buffering (proven config).
// C = A[M,K]*B[Nc,K]^T (+bias)(+relu). Block tile BM x 64, BK=32.
// mode=1 (qkv): q columns pre-scaled by QSCALE, whole output tf32-rounded.
// ======================================================================
#define STR 44   // smem row stride in floats

template<int BM>
__global__ void __launch_bounds__(BM * 2) gemm_tc(
    const float* __restrict__ A, const float* __restrict__ B,
    const float* __restrict__ bias, float* __restrict__ C,
    int M, int Nc, int K, int relu, int kslice, int mode)
{
    extern __shared__ float smem[];
    float* As = smem;                  // [2][BM][STR]
    float* Bs = smem + 2 * BM * STR;   // [2][64][STR]
    const int THREADS = BM * 2;

    const int tid = threadIdx.x;
    const int wid = tid >> 5, lane = tid & 31;
    const int g = lane >> 2, t = lane & 3;
    const int warp_m = wid >> 1, warp_n = wid & 1;
    const int row0 = blockIdx.y * BM, col0 = blockIdx.x * 64;
    const int kbeg = blockIdx.z * kslice;
    const int niter = kslice / 32;
    C += (size_t)blockIdx.z * M * Nc;

    const u32 sAa = smem_u32(As), sBa = smem_u32(Bs);

    float acc[2][4][4];
#pragma unroll
    for (int mt = 0; mt < 2; mt++)
#pragma unroll
        for (int nt = 0; nt < 4; nt++)
#pragma unroll
            for (int j = 0; j < 4; j++) acc[mt][nt][j] = 0.0f;

    auto issue = [&](int it, int buf) {
        const float* abase = A + (size_t)row0 * K + kbeg + it * 32;
        u32 ad = sAa + buf * BM * STR * 4;
#pragma unroll
        for (int i = 0; i < 4; i++) {
            int c = tid + i * THREADS;          // BM*8 chunks
            int rr = c >> 3, kc = (c & 7) * 4;
            cp16(ad + (rr * STR + kc) * 4, abase + (size_t)rr * K + kc);
        }
        const float* bbase = B + (size_t)col0 * K + kbeg + it * 32;
        u32 bd = sBa + buf * 64 * STR * 4;
#pragma unroll
        for (int i = 0; i < 512 / (BM * 2); i++) {
            int c = tid + i * THREADS;          // 512 chunks
            int rr = c >> 3, kc = (c & 7) * 4;
            cp16(bd + (rr * STR + kc) * 4, bbase + (size_t)rr * K + kc);
        }
        cpcommit();
    };

    issue(0, 0);
    for (int it = 0; it < niter; it++) {
        if (it + 1 < niter) issue(it + 1, (it + 1) & 1);
        if (it + 1 < niter) cpwait1(); else cpwait0();
        __syncthreads();

        const float* Ab = As + (it & 1) * BM * STR;
        const float* Bb = Bs + (it & 1) * 64 * STR;
#pragma unroll
        for (int ks = 0; ks < 4; ks++) {
            u32 af[2][4];
#pragma unroll
            for (int mt = 0; mt < 2; mt++) {
                int rb = warp_m * 32 + mt * 16;
                af[mt][0] = f2tf(Ab[(rb + g) * STR + ks * 8 + t]);
                af[mt][1] = f2tf(Ab[(rb + g + 8) * STR + ks * 8 + t]);
                af[mt][2] = f2tf(Ab[(rb + g) * STR + ks * 8 + t + 4]);
                af[mt][3] = f2tf(Ab[(rb + g + 8) * STR + ks * 8 + t + 4]);
            }
#pragma unroll
            for (int nt = 0; nt < 4; nt++) {
                int nb = warp_n * 32 + nt * 8;
                u32 b0 = f2tf(Bb[(nb + g) * STR + ks * 8 + t]);
                u32 b1 = f2tf(Bb[(nb + g) * STR + ks * 8 + t + 4]);
#pragma unroll
                for (int mt = 0; mt < 2; mt++)
                    mma_tf32(acc[mt][nt][0], acc[mt][nt][1], acc[mt][nt][2], acc[mt][nt][3],
                             af[mt][0], af[mt][1], af[mt][2], af[mt][3], b0, b1);
            }
        }
        __syncthreads();
    }

#pragma unroll
    for (int mt = 0; mt < 2; mt++) {
        int r0 = row0 + warp_m * 32 + mt * 16 + g;
#pragma unroll
        for (int nt = 0; nt < 4; nt++) {
            int c0i = col0 + warp_n * 32 + nt * 8 + 2 * t;
            float b0 = 0.f, b1 = 0.f;
            if (bias) { b0 = bias[c0i]; b1 = bias[c0i + 1]; }
            float v0 = acc[mt][nt][0] + b0, v1 = acc[mt][nt][1] + b1;
            float v2 = acc[mt][nt][2] + b0, v3 = acc[mt][nt][3] + b1;
            if (relu) {
                v0 = fmaxf(v0, 0.f); v1 = fmaxf(v1, 0.f);
                v2 = fmaxf(v2, 0.f); v3 = fmaxf(v3, 0.f);
            }
            if (mode) {   // qkv: pre-round (and pre-scale q by QSCALE)
                float s = (c0i < DD) ? QSCALE : 1.0f;
                v0 = __uint_as_float(f2tf(v0 * s));
                v1 = __uint_as_float(f2tf(v1 * s));
                v2 = __uint_as_float(f2tf(v2 * s));
                v3 = __uint_as_float(f2tf(v3 * s));
            }
            *(float2*)&C[(size_t)r0 * Nc + c0i] = make_float2(v0, v1);
            *(float2*)&C[(size_t)(r0 + 8) * Nc + c0i] = make_float2(v2, v3);
        }
    }
}

// ======================================================================
// Wide tf32 GEMM: block tile 128x128, BK=32, 256 threads (8 warps 4x2),
// warp tile 32x64 = 2 m16 x 8 n8. For big-N GEMMs (ffn1).
// ======================================================================
__global__ void __launch_bounds__(256) gemm_tc_w(
    const float* __restrict__ A, const float* __restrict__ B,
    const float* __restrict__ bias, float* __restrict__ C,
    int M, int Nc, int K, int relu)
{
    extern __shared__ float smem[];
    float* As = smem;                    // [2][128][STR]
    float* Bs = smem + 2 * 128 * STR;    // [2][128][STR]

    const int tid = threadIdx.x;
    const int wid = tid >> 5, lane = tid & 31;
    const int g = lane >> 2, t = lane & 3;
    const int warp_m = wid >> 1, warp_n = wid & 1;
    const int row0 = blockIdx.y * 128, col0 = blockIdx.x * 128;
    const int niter = K / 32;

    const u32 sAa = smem_u32(As), sBa = smem_u32(Bs);

    float acc[2][8][4];
#pragma unroll
    for (int mt = 0; mt < 2; mt++)
#pragma unroll
        for (int nt = 0; nt < 8; nt++)
#pragma unroll
            for (int j = 0; j < 4; j++) acc[mt][nt][j] = 0.0f;

    auto issue = [&](int it, int buf) {
        const float* abase = A + (size_t)row0 * K + it * 32;
        u32 ad = sAa + buf * 128 * STR * 4;
#pragma unroll
        for (int i = 0; i < 4; i++) {
            int c = tid + i * 256;              // 1024 chunks
            int rr = c >> 3, kc = (c & 7) * 4;
            cp16(ad + (rr * STR + kc) * 4, abase + (size_t)rr * K + kc);
        }
        const float* bbase = B + (size_t)col0 * K + it * 32;
        u32 bd = sBa + buf * 128 * STR * 4;
#pragma unroll
        for (int i = 0; i < 4; i++) {
            int c = tid + i * 256;              // 1024 chunks
            int rr = c >> 3, kc = (c & 7) * 4;
            cp16(bd + (rr * STR + kc) * 4, bbase + (size_t)rr * K + kc);
        }
        cpcommit();
    };

    issue(0, 0);
    for (int it = 0; it < niter; it++) {
        if (it + 1 < niter) issue(it + 1, (it + 1) & 1);
        if (it + 1 < niter) cpwait1(); else cpwait0();
        __syncthreads();

        const float* Ab = As + (it & 1) * 128 * STR;
        const float* Bb = Bs + (it & 1) * 128 * STR;
#pragma unroll
        for (int ks = 0; ks < 4; ks++) {
            u32 af[2][4];
#pragma unroll
            for (int mt = 0; mt < 2; mt++) {
                int rb = warp_m * 32 + mt * 16;
                af[mt][0] = f2tf(Ab[(rb + g) * STR + ks * 8 + t]);
                af[mt][1] = f2tf(Ab[(rb + g + 8) * STR + ks * 8 + t]);
                af[mt][2] = f2tf(Ab[(rb + g) * STR + ks * 8 + t + 4]);
                af[mt][3] = f2tf(Ab[(rb + g + 8) * STR + ks * 8 + t + 4]);
            }
#pragma unroll
            for (int nt = 0; nt < 8; nt++) {
                int nb = warp_n * 64 + nt * 8;
                u32 b0 = f2tf(Bb[(nb + g) * STR + ks * 8 + t]);
                u32 b1 = f2tf(Bb[(nb + g) * STR + ks * 8 + t + 4]);
#pragma unroll
                for (int mt = 0; mt < 2; mt++)
                    mma_tf32(acc[mt][nt][0], acc[mt][nt][1], acc[mt][nt][2], acc[mt][nt][3],
                             af[mt][0], af[mt][1], af[mt][2], af[mt][3], b0, b1);
            }
        }
        __syncthreads();
    }

#pragma unroll
    for (int mt = 0; mt < 2; mt++) {
        int r0 = row0 + warp_m * 32 + mt * 16 + g;
#pragma unroll
        for (int nt = 0; nt < 8; nt++) {
            int c0i = col0 + warp_n * 64 + nt * 8 + 2 * t;
            float b0 = 0.f, b1 = 0.f;
            if (bias) { b0 = bias[c0i]; b1 = bias[c0i + 1]; }
            float v0 = acc[mt][nt][0] + b0, v1 = acc[mt][nt][1] + b1;
            float v2 = acc[mt][nt][2] + b0, v3 = acc[mt][nt][3] + b1;
            if (relu) {
                v0 = fmaxf(v0, 0.f); v1 = fmaxf(v1, 0.f);
                v2 = fmaxf(v2, 0.f); v3 = fmaxf(v3, 0.f);
            }
            *(float2*)&C[(size_t)r0 * Nc + c0i] = make_float2(v0, v1);
            *(float2*)&C[(size_t)(r0 + 8) * Nc + c0i] = make_float2(v2, v3);
        }
    }
}

// ======================================================================
// Flash attention, tf32 mma, cp.async double-buffered K/V, K-split x2.
// Fixed-base softmax via ex2 (q pre-scaled by log2e/sqrt(dh)).
// P stored raw fp32 via st.shared.v2. 128 queries x head x half keys.
// ======================================================================
#define PSTR 36   // sP row stride (36 mod 32 == 4 -> conflict-free frag reads)

__global__ void __launch_bounds__(256) attn_tc(const float* __restrict__ qkv,
                                               float* __restrict__ pl,
                                               float* __restrict__ pacc)
{
    extern __shared__ float smem[];
    float* sK = smem;                   // [2][64][STR]
    float* sV = smem + 2 * 64 * STR;    // [2][64][STR]
    float* sQ = smem + 4 * 64 * STR;    // [QB][STR], reused as sP [QB][PSTR]
    float* sPf = sQ;
    u32*   sP = (u32*)sQ;

    const int h = blockIdx.y, z = blockIdx.z;
    const int q0 = blockIdx.x * QB;
    const int tid = threadIdx.x;
    const int wid = tid >> 5, lane = tid & 31;
    const int g = lane >> 2, t = lane & 3;
    const int rb = wid * 16;

    const int qoff = h * 32;
    const int koff = DD + h * 32;
    const int voff = 2 * DD + h * 32;
    const int kt_beg = z * KT_PER, kt_end = kt_beg + KT_PER;

    const u32 sKa = smem_u32(sK), sVa = smem_u32(sV), sQa = smem_u32(sQ);

    // stage Q
#pragma unroll
    for (int i = 0; i < QB * 8 / 256; i++) {
        int c = tid + i * 256;
        int rr = c >> 3, kc = (c & 7) * 4;
        cp16(sQa + (rr * STR + kc) * 4, &qkv[(size_t)(q0 + rr) * 384 + qoff + kc]);
    }
    cpcommit();

    auto issueKV = [&](int kt, int buf) {
#pragma unroll
        for (int i = 0; i < 2; i++) {
            int c = tid + i * 256;                  // 512 chunks (64 rows x 8)
            int rr = c >> 3, kc = (c & 7) * 4;
            const float* base = &qkv[(size_t)(kt * 64 + rr) * 384];
            cp16(sKa + (buf * 64 * STR + rr * STR + kc) * 4, base + koff + kc);
            cp16(sVa + (buf * 64 * STR + rr * STR + kc) * 4, base + voff + kc);
        }
        cpcommit();
    };

    issueKV(kt_beg, 0);
    cpwait1();
    __syncthreads();

    // Q fragments (already tf32-rounded and QSCALE-scaled)
    u32 qf[4][4];
#pragma unroll
    for (int ks = 0; ks < 4; ks++) {
        qf[ks][0] = __float_as_uint(sQ[(rb + g) * STR + ks * 8 + t]);
        qf[ks][1] = __float_as_uint(sQ[(rb + g + 8) * STR + ks * 8 + t]);
        qf[ks][2] = __float_as_uint(sQ[(rb + g) * STR + ks * 8 + t + 4]);
        qf[ks][3] = __float_as_uint(sQ[(rb + g + 8) * STR + ks * 8 + t + 4]);
    }

    float O[4][4];
#pragma unroll
    for (int nt = 0; nt < 4; nt++)
#pragma unroll
        for (int j = 0; j < 4; j++) O[nt][j] = 0.0f;
    float lg = 0.0f, lg8 = 0.0f;

    for (int kt = kt_beg; kt < kt_end; kt++) {
        if (kt + 1 < kt_end) issueKV(kt + 1, (kt + 1) & 1);
        if (kt + 1 < kt_end) cpwait1(); else cpwait0();
        __syncthreads();

        const float* K_ = sK + (kt & 1) * 64 * STR;
        const float* V_ = sV + (kt & 1) * 64 * STR;

        // S = Q K^T (16 x 64 per warp), base-2 domain
        float sc[8][4];
#pragma unroll
        for (int nt = 0; nt < 8; nt++)
#pragma unroll
            for (int j = 0; j < 4; j++) sc[nt][j] = 0.0f;
#pragma unroll
        for (int ks = 0; ks < 4; ks++) {
#pragma unroll
            for (int nt = 0; nt < 8; nt++) {
                u32 b0 = __float_as_uint(K_[(nt * 8 + g) * STR + ks * 8 + t]);
                u32 b1 = __float_as_uint(K_[(nt * 8 + g) * STR + ks * 8 + t + 4]);
                mma_tf32(sc[nt][0], sc[nt][1], sc[nt][2], sc[nt][3],
                         qf[ks][0], qf[ks][1], qf[ks][2], qf[ks][3], b0, b1);
            }
        }

        // P = 2^S -> sP via v2 stores; accumulate row sums in fp32
#pragma unroll
        for (int nt = 0; nt < 8; nt++) {
            float p0 = ex2(sc[nt][0]);
            float p1 = ex2(sc[nt][1]);
            float p2 = ex2(sc[nt][2]);
            float p3 = ex2(sc[nt][3]);
            lg += p0 + p1; lg8 += p2 + p3;
            int cc = nt * 8 + 2 * t;
            *(float2*)&sPf[(rb + g) * PSTR + cc] = make_float2(p0, p1);
            *(float2*)&sPf[(rb + g + 8) * PSTR + cc] = make_float2(p2, p3);
        }
        __syncwarp();

        // O += P V
#pragma unroll
        for (int ks = 0; ks < 8; ks++) {
            u32 a0 = sP[(rb + g) * PSTR + ks * 8 + t];
            u32 a1 = sP[(rb + g + 8) * PSTR + ks * 8 + t];
            u32 a2 = sP[(rb + g) * PSTR + ks * 8 + t + 4];
            u32 a3 = sP[(rb + g + 8) * PSTR + ks * 8 + t + 4];
#pragma unroll
            for (int nt = 0; nt < 4; nt++) {
                u32 b0 = __float_as_uint(V_[(ks * 8 + t) * STR + nt * 8 + g]);
                u32 b1 = __float_as_uint(V_[(ks * 8 + t + 4) * STR + nt * 8 + g]);
                mma_tf32(O[nt][0], O[nt][1], O[nt][2], O[nt][3],
                         a0, a1, a2, a3, b0, b1);
            }
        }
        __syncthreads();
    }

    // quad-reduce l; write unnormalized partials
    lg  += __shfl_xor_sync(0xffffffffu, lg, 1);
    lg  += __shfl_xor_sync(0xffffffffu, lg, 2);
    lg8 += __shfl_xor_sync(0xffffffffu, lg8, 1);
    lg8 += __shfl_xor_sync(0xffffffffu, lg8, 2);

    const int prow = (z * HH + h) * NN + q0 + rb + g;   // row index in partials
    if (t == 0) {
        pl[prow] = lg;       pl[prow + 8] = lg8;
    }
    float* op0 = pacc + (size_t)prow * 32;
    float* op8 = pacc + (size_t)(prow + 8) * 32;
#pragma unroll
    for (int nt = 0; nt < 4; nt++) {
        int cc = nt * 8 + 2 * t;
        *(float2*)&op0[cc] = make_float2(O[nt][0], O[nt][1]);
        *(float2*)&op8[cc] = make_float2(O[nt][2], O[nt][3]);
    }
}

// ======================================================================
// Fused combine + out_proj + residual + LayerNorm1:
// y = LN(x + (ctx @ W^T + b)), ctx = (pacc0+pacc1)/(l0+l1).
// Block = 64 rows x FULL 128 cols (so LN is block-local). 256 threads,
// 8 warps (warp_m 0..3 x warp_n 0..1), warp tile 16x64 (8 n8 tiles).
// ======================================================================
__global__ void __launch_bounds__(256) outproj_ln_fused(
    const float* __restrict__ pl, const float* __restrict__ pacc,
    const float* __restrict__ W, const float* __restrict__ bias,
    const float* __restrict__ x,
    const float* __restrict__ lng, const float* __restrict__ lnb,
    float* __restrict__ Y)
{
    extern __shared__ float smem[];
    constexpr int AST = DD + 4;          // 132
    float* As  = smem;                   // [64][AST] ctx
    float* Bs  = smem + 64 * AST;        // [128][AST] weights
    float* red = smem + (64 + 128) * AST; // [64][2][2] LN partials

    const int tid = threadIdx.x;
    const int wid = tid >> 5, lane = tid & 31;
    const int g = lane >> 2, t = lane & 3;
    const int warp_m = wid >> 1, warp_n = wid & 1;
    const int row0 = blockIdx.x * 64;
    const u32 sBa = smem_u32(Bs);
    const int OFF = HH * NN;

    // issue B (all 128 weight rows) async first: 128*32 = 4096 chunks
#pragma unroll
    for (int i = 0; i < 16; i++) {
        int c = tid + i * 256;
        int rr = c >> 5, kc = (c & 31) * 4;
        cp16(sBa + (rr * AST + kc) * 4, W + (size_t)rr * DD + kc);
    }
    cpcommit();

    // stage A = normalized ctx from partials (overlaps B flight)
#pragma unroll
    for (int i = 0; i < 8; i++) {
        int c = tid + i * 256;                   // 2048 chunks
        int rr = c >> 5, kc = (c & 31) * 4;      // kc in [0,128)
        int h = kc >> 5, cc = kc & 31;
        int n = row0 + rr;
        int pr = h * NN + n;
        float l = pl[pr] + pl[OFF + pr];
        float inv = 1.0f / l;
        const float4 a0 = *(const float4*)&pacc[(size_t)pr * 32 + cc];
        const float4 a1 = *(const float4*)&pacc[(size_t)(OFF + pr) * 32 + cc];
        float4 v;
        v.x = (a0.x + a1.x) * inv; v.y = (a0.y + a1.y) * inv;
        v.z = (a0.z + a1.z) * inv; v.w = (a0.w + a1.w) * inv;
        *(float4*)&As[rr * AST + kc] = v;
    }
    cpwait0();
    __syncthreads();

    float acc[8][4];
#pragma unroll
    for (int nt = 0; nt < 8; nt++)
#pragma unroll
        for (int j = 0; j < 4; j++) acc[nt][j] = 0.0f;

#pragma unroll
    for (int ks = 0; ks < DD / 8; ks++) {
        int rbm = warp_m * 16;
        u32 a0 = f2tf(As[(rbm + g) * AST + ks * 8 + t]);
        u32 a1 = f2tf(As[(rbm + g + 8) * AST + ks * 8 + t]);
        u32 a2 = f2tf(As[(rbm + g) * AST + ks * 8 + t + 4]);
        u32 a3 = f2tf(As[(rbm + g + 8) * AST + ks * 8 + t + 4]);
#pragma unroll
        for (int nt = 0; nt < 8; nt++) {
            int nb = warp_n * 64 + nt * 8;
            u32 b0 = f2tf(Bs[(nb + g) * AST + ks * 8 + t]);
            u32 b1 = f2tf(Bs[(nb + g) * AST + ks * 8 + t + 4]);
            mma_tf32(acc[nt][0], acc[nt][1], acc[nt][2], acc[nt][3],
                     a0, a1, a2, a3, b0, b1);
        }
    }

    // epilogue: v = acc + bias + x, then LN over the 128 cols of each row
    const int r0 = row0 + warp_m * 16 + g;       // global rows r0, r0+8
    const int rl0 = warp_m * 16 + g;             // local rows
    float s0 = 0.f, q0v = 0.f, s8 = 0.f, q8v = 0.f;
#pragma unroll
    for (int nt = 0; nt < 8; nt++) {
        int c0i = warp_n * 64 + nt * 8 + 2 * t;
        float b0 = bias[c0i], b1 = bias[c0i + 1];
        float2 x0 = *(const float2*)&x[(size_t)r0 * DD + c0i];
        float2 x8 = *(const float2*)&x[(size_t)(r0 + 8) * DD + c0i];
        acc[nt][0] += b0 + x0.x;  acc[nt][1] += b1 + x0.y;
        acc[nt][2] += b0 + x8.x;  acc[nt][3] += b1 + x8.y;
        s0  += acc[nt][0] + acc[nt][1];
        q0v += acc[nt][0] * acc[nt][0] + acc[nt][1] * acc[nt][1];
        s8  += acc[nt][2] + acc[nt][3];
        q8v += acc[nt][2] * acc[nt][2] + acc[nt][3] * acc[nt][3];
    }
    // reduce over the 4 t-lanes (same g)
#pragma unroll
    for (int off = 1; off <= 2; off <<= 1) {
        s0  += __shfl_xor_sync(0xffffffffu, s0, off);
        q0v += __shfl_xor_sync(0xffffffffu, q0v, off);
        s8  += __shfl_xor_sync(0xffffffffu, s8, off);
        q8v += __shfl_xor_sync(0xffffffffu, q8v, off);
    }
    if (t == 0) {
        red[(rl0 * 2 + warp_n) * 2 + 0] = s0;
        red[(rl0 * 2 + warp_n) * 2 + 1] = q0v;
        red[((rl0 + 8) * 2 + warp_n) * 2 + 0] = s8;
        red[((rl0 + 8) * 2 + warp_n) * 2 + 1] = q8v;
    }
    __syncthreads();
    float st0 = red[(rl0 * 2) * 2] + red[(rl0 * 2 + 1) * 2];
    float qt0 = red[(rl0 * 2) * 2 + 1] + red[(rl0 * 2 + 1) * 2 + 1];
    float st8 = red[((rl0 + 8) * 2) * 2] + red[((rl0 + 8) * 2 + 1) * 2];
    float qt8 = red[((rl0 + 8) * 2) * 2 + 1] + red[((rl0 + 8) * 2 + 1) * 2 + 1];
    float mu0 = st0 * (1.0f / DD), mu8 = st8 * (1.0f / DD);
    float iv0 = rsqrtf(qt0 * (1.0f / DD) - mu0 * mu0 + LNEPS);
    float iv8 = rsqrtf(qt8 * (1.0f / DD) - mu8 * mu8 + LNEPS);

#pragma unroll
    for (int nt = 0; nt < 8; nt++) {
        int c0i = warp_n * 64 + nt * 8 + 2 * t;
        float2 gw = *(const float2*)&lng[c0i];
        float2 bw = *(const float2*)&lnb[c0i];
        float y0 = (acc[nt][0] - mu0) * iv0 * gw.x + bw.x;
        float y1 = (acc[nt][1] - mu0) * iv0 * gw.y + bw.y;
        float y2 = (acc[nt][2] - mu8) * iv8 * gw.x + bw.x;
        float y3 = (acc[nt][3] - mu8) * iv8 * gw.y + bw.y;
        *(float2*)&Y[(size_t)r0 * DD + c0i] = make_float2(y0, y1);
        *(float2*)&Y[(size_t)(r0 + 8) * DD + c0i] = make_float2(y2, y3);
    }
}

// ---------------- residual + sum(FSPLIT) + LayerNorm ----------------------
__global__ void __launch_bounds__(256) ln_sum4_kernel(
    const float* __restrict__ x, const float* __restrict__ parts,
    const float* __restrict__ fb, const float* __restrict__ g,
    const float* __restrict__ b, float* __restrict__ out)
{
    int row = blockIdx.x * 8 + (threadIdx.x >> 5);
    int lane = threadIdx.x & 31;
    size_t i = (size_t)row * 32 + lane;
    const size_t ps = (size_t)NN * 32;    // float4 stride between partials
    const float4* p4 = (const float4*)parts;
    float4 v = ((const float4*)x)[i];
    float4 fbv = ((const float4*)fb)[lane];
    v.x += fbv.x; v.y += fbv.y; v.z += fbv.z; v.w += fbv.w;
#pragma unroll
    for (int zz = 0; zz < FSPLIT; zz++) {
        float4 p = p4[i + zz * ps];
        v.x += p.x; v.y += p.y; v.z += p.z; v.w += p.w;
    }

    float s = v.x + v.y + v.z + v.w;
    float s2 = v.x * v.x + v.y * v.y + v.z * v.z + v.w * v.w;
#pragma unroll
    for (int off = 16; off > 0; off >>= 1) {
        s  += __shfl_xor_sync(0xffffffffu, s, off);
        s2 += __shfl_xor_sync(0xffffffffu, s2, off);
    }
    float mu = s * (1.0f / DD);
    float var = s2 * (1.0f / DD) - mu * mu;
    float inv = rsqrtf(var + LNEPS);

    float4 gw = ((const float4*)g)[lane];
    float4 bw = ((const float4*)b)[lane];
    float4 o;
    o.x = (v.x - mu) * inv * gw.x + bw.x;
    o.y = (v.y - mu) * inv * gw.y + bw.y;
    o.z = (v.z - mu) * inv * gw.z + bw.z;
    o.w = (v.w - mu) * inv * gw.w + bw.w;
    ((float4*)out)[i] = o;
}

// ---------------- GCN graph preprocessing (side stream) --------------------
__global__ void zero_cnt_kernel() {
    g_cnt[blockIdx.x * 256 + threadIdx.x] = 0;
}
__global__ void count_kernel(const int* __restrict__ dst) {
    int e = blockIdx.x * blockDim.x + threadIdx.x;
    if (e < EE) atomicAdd(&g_cnt[dst[e]], 1);
}
__global__ void scan_kernel() {
    __shared__ int sh[1024];
    int t = threadIdx.x;
    int base = t * 4;
    int c0 = g_cnt[base + 0], c1 = g_cnt[base + 1];
    int c2 = g_cnt[base + 2], c3 = g_cnt[base + 3];
    g_dinv[base + 0] = rsqrtf((float)c0 + 1.0f);
    g_dinv[base + 1] = rsqrtf((float)c1 + 1.0f);
    g_dinv[base + 2] = rsqrtf((float)c2 + 1.0f);
    g_dinv[base + 3] = rsqrtf((float)c3 + 1.0f);
    int local = c0 + c1 + c2 + c3;
    sh[t] = local;
    __syncthreads();
    for (int off = 1; off < 1024; off <<= 1) {
        int v = (t >= off) ? sh[t - off] : 0;
        __syncthreads();
        sh[t] += v;
        __syncthreads();
    }
    int excl = sh[t] - local;
    int p0 = excl, p1 = excl + c0, p2 = p1 + c1, p3 = p2 + c2;
    g_rowptr[base + 0] = p0; g_rowptr[base + 1] = p1;
    g_rowptr[base + 2] = p2; g_rowptr[base + 3] = p3;
    g_fillpos[base + 0] = p0; g_fillpos[base + 1] = p1;
    g_fillpos[base + 2] = p2; g_fillpos[base + 3] = p3;
    if (t == 1023) g_rowptr[NN] = excl + local;
}
__global__ void fill_kernel(const int* __restrict__ src, const int* __restrict__ dst) {
    int e = blockIdx.x * blockDim.x + threadIdx.x;
    if (e < EE) {
        int d = dst[e];
        int pos = atomicAdd(&g_fillpos[d], 1);
        g_col[pos] = src[e];
    }
}

// ---------------- GCN aggregation: gather over CSR, 2-deep prefetch --------
template<int F, bool RELU>
__global__ void gather_kernel(const float* __restrict__ hw,
                              const float* __restrict__ bias,
                              float* __restrict__ out)
{
    constexpr int TPR = F / 4;
    constexpr int RPB = 256 / TPR;
    int tid = threadIdx.x;
    int r = blockIdx.x * RPB + tid / TPR;
    int lane = tid % TPR;
    const float4* hw4 = (const float4*)hw;

    float dr = g_dinv[r];
    float4 acc = hw4[(size_t)r * TPR + lane];
    float selfw = dr * dr;
    acc.x *= selfw; acc.y *= selfw; acc.z *= selfw; acc.w *= selfw;

    int p0 = g_rowptr[r], p1 = g_rowptr[r + 1];
    int cnt = p1 - p0;
    if (cnt > 0) {
        // 2-deep software pipeline: slots A (p) and B (p+1) in flight
        int sA = g_col[p0];
        float dA = g_dinv[sA];
        float4 hA = hw4[(size_t)sA * TPR + lane];
        int sB; float dB; float4 hB;
        if (cnt > 1) {
            sB = g_col[p0 + 1];
            dB = g_dinv[sB];
            hB = hw4[(size_t)sB * TPR + lane];
        }
        for (int p = p0 + 2; p < p1; p++) {
            int sC = g_col[p];
            float dC = g_dinv[sC];
            float4 hC = hw4[(size_t)sC * TPR + lane];
            float nrm = dA * dr;
            acc.x += nrm * hA.x; acc.y += nrm * hA.y;
            acc.z += nrm * hA.z; acc.w += nrm * hA.w;
            hA = hB; dA = dB;
            hB = hC; dB = dC;
        }
        {
            float nrm = dA * dr;
            acc.x += nrm * hA.x; acc.y += nrm * hA.y;
            acc.z += nrm * hA.z; acc.w += nrm * hA.w;
        }
        if (cnt > 1) {
            float nrm = dB * dr;
            acc.x += nrm * hB.x; acc.y += nrm * hB.y;
            acc.z += nrm * hB.z; acc.w += nrm * hB.w;
        }
    }
    if (bias) {
        float4 bb = *(const float4*)&bias[lane * 4];
        acc.x += bb.x; acc.y += bb.y; acc.z += bb.z; acc.w += bb.w;
    }
    if (RELU) {
        acc.x = fmaxf(acc.x, 0.f); acc.y = fmaxf(acc.y, 0.f);
        acc.z = fmaxf(acc.z, 0.f); acc.w = fmaxf(acc.w, 0.f);
    }
    *(float4*)&out[(size_t)r * F + lane * 4] = acc;
}

// ---------------- launch ---------------------------------------------------
extern "C" void kernel_launch(void* const* d_in, const int* in_sizes, int n_in,
                              void* d_out, int out_size)
{
    const float* x          = (const float*)d_in[0];
    const int*   edge_index = (const int*)  d_in[1];
    const float* in_proj_w  = (const float*)d_in[2];
    const float* in_proj_b  = (const float*)d_in[3];
    const float* out_proj_w = (const float*)d_in[4];
    const float* out_proj_b = (const float*)d_in[5];
    const float* ln1_g      = (const float*)d_in[6];
    const float* ln1_b      = (const float*)d_in[7];
    const float* ffn_w1     = (const float*)d_in[8];
    const float* ffn_b1     = (const float*)d_in[9];
    const float* ffn_w2     = (const float*)d_in[10];
    const float* ffn_b2     = (const float*)d_in[11];
    const float* ln2_g      = (const float*)d_in[12];
    const float* ln2_b      = (const float*)d_in[13];
    const float* gcn1_w     = (const float*)d_in[14];
    const float* gcn1_b     = (const float*)d_in[15];
    const float* gcn2_w     = (const float*)d_in[16];
    const float* gcn2_b     = (const float*)d_in[17];
    const float* gcn3_w     = (const float*)d_in[18];
    const float* gcn3_b     = (const float*)d_in[19];
    float* out = (float*)d_out;

    const int* src = edge_index;
    const int* dst = edge_index + EE;

    float *p_qkv, *p_tmp, *p_y, *p_mid, *p_z, *p_f2, *p_hw, *p_h1, *p_h2;
    float *p_pl, *p_pacc;
    cudaGetSymbolAddress((void**)&p_qkv,  g_qkv);
    cudaGetSymbolAddress((void**)&p_tmp,  g_tmp);
    cudaGetSymbolAddress((void**)&p_y,    g_y);
    cudaGetSymbolAddress((void**)&p_mid,  g_mid);
    cudaGetSymbolAddress((void**)&p_z,    g_z);
    cudaGetSymbolAddress((void**)&p_f2,   g_f2);
    cudaGetSymbolAddress((void**)&p_hw,   g_hw);
    cudaGetSymbolAddress((void**)&p_h1,   g_h1);
    cudaGetSymbolAddress((void**)&p_h2,   g_h2);
    cudaGetSymbolAddress((void**)&p_pl,   g_pl);
    cudaGetSymbolAddress((void**)&p_pacc, g_pacc);

    const int SM_G128 = (2 * 128 * STR + 2 * 64 * STR) * 4;   // 67584
    const int SM_G64  = (2 * 64 * STR + 2 * 64 * STR) * 4;    // 45056
    const int SM_GW   = (4 * 128 * STR) * 4;                  // 90112
    const int SM_ATTN = (4 * 64 * STR + QB * STR) * 4;        // 67584
    const int SM_OPLN = ((64 + 128) * (DD + 4) + 64 * 4) * 4; // 102400

    cudaFuncSetAttribute(gemm_tc<128>, cudaFuncAttributeMaxDynamicSharedMemorySize, SM_G128);
    cudaFuncSetAttribute(gemm_tc<64>,  cudaFuncAttributeMaxDynamicSharedMemorySize, SM_G64);
    cudaFuncSetAttribute(gemm_tc_w,    cudaFuncAttributeMaxDynamicSharedMemorySize, SM_GW);
    cudaFuncSetAttribute(attn_tc,      cudaFuncAttributeMaxDynamicSharedMemorySize, SM_ATTN);
    cudaFuncSetAttribute(outproj_ln_fused, cudaFuncAttributeMaxDynamicSharedMemorySize, SM_OPLN);

    // side stream + fork/join events (created once on the uncaptured call)
    static cudaStream_t s2 = nullptr;
    static cudaEvent_t evFork = nullptr, evJoin = nullptr;
    if (s2 == nullptr) {
        cudaStreamCreateWithFlags(&s2, cudaStreamNonBlocking);
        cudaEventCreateWithFlags(&evFork, cudaEventDisableTiming);
        cudaEventCreateWithFlags(&evJoin, cudaEventDisableTiming);
    }

    // ---- fork: graph preprocessing on side stream ----
    cudaEventRecord(evFork, 0);
    cudaStreamWaitEvent(s2, evFork, 0);
    zero_cnt_kernel<<<NN / 256, 256, 0, s2>>>();
    count_kernel<<<EE / 256, 256, 0, s2>>>(dst);
    scan_kernel<<<1, 1024, 0, s2>>>();
    fill_kernel<<<EE / 256, 256, 0, s2>>>(src, dst);
    cudaEventRecord(evJoin, s2);

    // ---- transformer encoder layer (main stream) ----
    gemm_tc<128><<<dim3(6, 32), 256, SM_G128>>>(x, in_proj_w, in_proj_b, p_qkv,
                                                NN, 384, DD, 0, DD, 1);
    attn_tc<<<dim3(NN / QB, HH, ZSPLIT), 256, SM_ATTN>>>(p_qkv, p_pl, p_pacc);
    outproj_ln_fused<<<64, 256, SM_OPLN>>>(p_pl, p_pacc, out_proj_w, out_proj_b,
                                           x, ln1_g, ln1_b, p_y);
    gemm_tc_w<<<dim3(DFF / 128, 32), 256, SM_GW>>>(p_y, ffn_w1, ffn_b1, p_mid,
                                                   NN, DFF, DD, 1);
    gemm_tc<128><<<dim3(2, 32, FSPLIT), 256, SM_G128>>>(p_mid, ffn_w2, nullptr, p_f2,
                                                        NN, DD, DFF, 0, DFF / FSPLIT, 0);
    ln_sum4_kernel<<<NN / 8, 256>>>(p_y, p_f2, ffn_b2, ln2_g, ln2_b, p_z);

    // ---- join: CSR must be ready before the first gather ----
    cudaStreamWaitEvent(0, evJoin, 0);

    // ---- GCN layer 1: aggregate z (128-wide) first, then project ----
    gather_kernel<DD, false><<<NN / 8, 256>>>(p_z, nullptr, p_tmp);
    gemm_tc<64><<<dim3(4, 64), 128, SM_G64>>>(p_tmp, gcn1_w, gcn1_b, p_h1,
                                              NN, HID, DD, 1, DD, 0);

    // ---- GCN layer 2: project then aggregate (bias+relu in gather) ----
    gemm_tc<64><<<dim3(4, 64), 128, SM_G64>>>(p_h1, gcn2_w, nullptr, p_hw,
                                              NN, HID, HID, 0, HID, 0);
    gather_kernel<HID, true><<<NN / 4, 256>>>(p_hw, gcn2_b, p_h2);

    // ---- GCN layer 3: project (64-wide) then aggregate ----
    gemm_tc<64><<<dim3(1, 64), 128, SM_G64>>>(p_h2, gcn3_w, nullptr, p_hw,
                                              NN, OUTD, HID, 0, HID, 0);
    gather_kernel<OUTD, false><<<NN / 16, 256>>>(p_hw, gcn3_b, out);
}